// round 11
// baseline (speedup 1.0000x reference)
#include <cuda_runtime.h>
#include <cuda_bf16.h>
#include <cstdint>

#define BATCH 1024
#define TT    133
#define DD    256
#define EE    512
#define SS    128
#define NUV   1152
#define MTOT  (BATCH*TT)     // 136192
#define INV_SQRT_S 0.08838834764831845f
#define EPSV  1e-5f

typedef unsigned long long ull;

// ---------------- scratch ----------------------------------------------------
__device__ float g_uv[(size_t)MTOT * NUV];
__device__ __align__(16) __nv_bfloat16 g_xh[(size_t)MTOT * DD];
__device__ __align__(16) __nv_bfloat16 g_xl[(size_t)MTOT * DD];
__device__ __align__(16) __nv_bfloat16 g_wh[(size_t)NUV * DD];
__device__ __align__(16) __nv_bfloat16 g_wl[(size_t)NUV * DD];
__device__ __align__(16) __nv_bfloat16 g_woh[(size_t)DD * EE];
__device__ __align__(16) __nv_bfloat16 g_wol[(size_t)DD * EE];
__device__ __align__(16) __nv_bfloat16 g_hh[(size_t)MTOT * EE];
__device__ __align__(16) __nv_bfloat16 g_hl[(size_t)MTOT * EE];

// ---------------- helpers ----------------------------------------------------
__device__ __forceinline__ uint32_t smem_u32(const void* p) {
    uint32_t a;
    asm("{ .reg .u64 t; cvta.to.shared.u64 t, %1; cvt.u32.u64 %0, t; }"
        : "=r"(a) : "l"(p));
    return a;
}
__device__ __forceinline__ float silu_f(float v) { return v / (1.0f + __expf(-v)); }
__device__ __forceinline__ void split1(float v, __nv_bfloat16 &h, __nv_bfloat16 &l) {
    h = __float2bfloat16(v);
    l = __float2bfloat16(v - __bfloat162float(h));
}
__device__ __forceinline__ void mma16816(float (&d)[4], const uint32_t (&a)[4],
                                         uint32_t b0, uint32_t b1) {
    asm volatile("mma.sync.aligned.m16n8k16.row.col.f32.bf16.bf16.f32 "
                 "{%0,%1,%2,%3}, {%4,%5,%6,%7}, {%8,%9}, {%0,%1,%2,%3};"
                 : "+f"(d[0]), "+f"(d[1]), "+f"(d[2]), "+f"(d[3])
                 : "r"(a[0]), "r"(a[1]), "r"(a[2]), "r"(a[3]), "r"(b0), "r"(b1));
}
__device__ __forceinline__ void ldmx4(uint32_t (&r)[4], uint32_t addr) {
    asm volatile("ldmatrix.sync.aligned.m8n8.x4.shared.b16 {%0,%1,%2,%3}, [%4];"
                 : "=r"(r[0]), "=r"(r[1]), "=r"(r[2]), "=r"(r[3]) : "r"(addr));
}
__device__ __forceinline__ void ldmx4t(uint32_t (&r)[4], uint32_t addr) {
    asm volatile("ldmatrix.sync.aligned.m8n8.x4.trans.shared.b16 {%0,%1,%2,%3}, [%4];"
                 : "=r"(r[0]), "=r"(r[1]), "=r"(r[2]), "=r"(r[3]) : "r"(addr));
}
#define CP_ASYNC16(s, g) \
    asm volatile("cp.async.cg.shared.global [%0], [%1], 16;" :: "r"(s), "l"(g))
#define CP_COMMIT() asm volatile("cp.async.commit_group;")
#define CP_WAIT3()  asm volatile("cp.async.wait_group 3;")

// ---------------- fused rnorm + x split --------------------------------------
__global__ void k_rnorm_split(const float* __restrict__ x, const float* __restrict__ g) {
    int row = blockIdx.x * 8 + threadIdx.y;
    int lane = threadIdx.x;
    const float4* xr = (const float4*)(x + (size_t)row * DD);
    float4 v0 = xr[lane], v1 = xr[lane + 32];
    float s = v0.x*v0.x + v0.y*v0.y + v0.z*v0.z + v0.w*v0.w
            + v1.x*v1.x + v1.y*v1.y + v1.z*v1.z + v1.w*v1.w;
#pragma unroll
    for (int o = 16; o; o >>= 1) s += __shfl_xor_sync(0xffffffffu, s, o);
    float sc = g[0] / fmaxf(sqrtf(s) * 0.0625f, EPSV);
    size_t base = (size_t)row * 64;
#pragma unroll
    for (int half = 0; half < 2; half++) {
        float4 v = half ? v1 : v0;
        size_t idx = base + lane + half * 32;
        __nv_bfloat16 h0,h1,h2,h3,l0,l1,l2,l3;
        split1(v.x*sc,h0,l0); split1(v.y*sc,h1,l1);
        split1(v.z*sc,h2,l2); split1(v.w*sc,h3,l3);
        __nv_bfloat162* dh = (__nv_bfloat162*)(g_xh + idx*4);
        __nv_bfloat162* dl = (__nv_bfloat162*)(g_xl + idx*4);
        dh[0] = __nv_bfloat162(h0,h1); dh[1] = __nv_bfloat162(h2,h3);
        dl[0] = __nv_bfloat162(l0,l1); dl[1] = __nv_bfloat162(l2,l3);
    }
}

// ---------------- weight split ------------------------------------------------
__global__ void k_split_w(const float* __restrict__ Wuv, const float* __restrict__ Wo) {
    int idx = blockIdx.x * 256 + threadIdx.x;
    const int N1 = NUV * DD / 4;
    const int N2 = DD * EE / 4;
    if (idx < N1) {
        float4 v = ((const float4*)Wuv)[idx];
        __nv_bfloat16 h0,h1,h2,h3,l0,l1,l2,l3;
        split1(v.x,h0,l0); split1(v.y,h1,l1); split1(v.z,h2,l2); split1(v.w,h3,l3);
        __nv_bfloat162* ph = (__nv_bfloat162*)(g_wh + (size_t)idx*4);
        __nv_bfloat162* pl = (__nv_bfloat162*)(g_wl + (size_t)idx*4);
        ph[0] = __nv_bfloat162(h0,h1); ph[1] = __nv_bfloat162(h2,h3);
        pl[0] = __nv_bfloat162(l0,l1); pl[1] = __nv_bfloat162(l2,l3);
    } else if (idx < N1 + N2) {
        int j = idx - N1;
        float4 v = ((const float4*)Wo)[j];
        __nv_bfloat16 h0,h1,h2,h3,l0,l1,l2,l3;
        split1(v.x,h0,l0); split1(v.y,h1,l1); split1(v.z,h2,l2); split1(v.w,h3,l3);
        __nv_bfloat162* ph = (__nv_bfloat162*)(g_woh + (size_t)j*4);
        __nv_bfloat162* pl = (__nv_bfloat162*)(g_wol + (size_t)j*4);
        ph[0] = __nv_bfloat162(h0,h1); ph[1] = __nv_bfloat162(h2,h3);
        pl[0] = __nv_bfloat162(l0,l1); pl[1] = __nv_bfloat162(l2,l3);
    }
}

// ---------------- GEMMs: 5-stage cp.async pipeline ---------------------------
// GEMM==0: g_uv = silu([xh|xl] @ [wh|wl]^T), K=256, N=1152
// GEMM==1: out  = [hh|hl] @ [woh|wol]^T + x*res, K=512, N=256
#define STRIDE   40
#define STG_B    10240                 // one 128x32 tile (128*40*2 bytes)
#define NSTG     5
#define GM_SMEM  (2 * NSTG * STG_B)    // 102400 bytes

template<int GEMM>
__global__ __launch_bounds__(256, 2)
void k_gemm_mma(const float* __restrict__ x, const float* __restrict__ res,
                float* __restrict__ outp_param) {
    constexpr int KREAL = (GEMM == 0) ? 256 : 512;
    constexpr int LDC   = (GEMM == 0) ? NUV : DD;
    constexpr int KC    = KREAL / 32;
    constexpr int NC    = 3 * KC;
    const __nv_bfloat16* Ah = (GEMM == 0) ? g_xh : g_hh;
    const __nv_bfloat16* Al = (GEMM == 0) ? g_xl : g_hl;
    const __nv_bfloat16* Bh = (GEMM == 0) ? g_wh : g_woh;
    const __nv_bfloat16* Bl = (GEMM == 0) ? g_wl : g_wol;
    float* outp = (GEMM == 0) ? g_uv : outp_param;   // device-side symbol ref!

    extern __shared__ __align__(16) char smc[];
    uint32_t sbase = smem_u32(smc);
    uint32_t sbB   = sbase + NSTG * STG_B;

    int tid = threadIdx.x, lane = tid & 31, wid = tid >> 5;
    int m0 = blockIdx.y * 128, n0 = blockIdx.x * 128;
    int wm = (wid & 1) * 64, wn = (wid >> 1) * 32;
    int qr = lane >> 2, qc = (lane & 3) * 2;

    int lrow = (tid * 2) >> 2;
    int lu   = (tid * 2) & 3;
    uint32_t soff0 = lrow * 80 + lu * 16;
    uint32_t soff1 = lrow * 80 + (lu + 1) * 16;

    uint32_t aoff = (uint32_t)((wm + (lane & 7) + ((lane >> 3) & 1) * 8) * 80
                               + ((lane >> 4) & 1) * 16);
    uint32_t boff = (uint32_t)((wn + ((lane >> 4) & 1) * 8 + (lane & 7)) * 80
                      + ((lane >> 3) & 1) * 16);

    float acc[4][4][4];
#pragma unroll
    for (int i = 0; i < 4; i++)
#pragma unroll
        for (int j = 0; j < 4; j++)
#pragma unroll
            for (int k = 0; k < 4; k++) acc[i][j][k] = 0.f;

#define G_ISSUE(c) do { \
    int st_ = (c) % NSTG; \
    int term = (c) / KC; \
    int kk = ((c) % KC) * 32; \
    const __nv_bfloat16* a_ = (term == 1) ? Al : Ah; \
    const __nv_bfloat16* b_ = (term == 2) ? Bl : Bh; \
    uint32_t sa_ = sbase + st_ * STG_B; \
    uint32_t sb_ = sbB   + st_ * STG_B; \
    CP_ASYNC16(sa_ + soff0, a_ + (size_t)(m0 + lrow) * KREAL + kk + lu * 8); \
    CP_ASYNC16(sa_ + soff1, a_ + (size_t)(m0 + lrow) * KREAL + kk + (lu + 1) * 8); \
    CP_ASYNC16(sb_ + soff0, b_ + (size_t)(n0 + lrow) * KREAL + kk + lu * 8); \
    CP_ASYNC16(sb_ + soff1, b_ + (size_t)(n0 + lrow) * KREAL + kk + (lu + 1) * 8); \
} while (0)

    G_ISSUE(0); CP_COMMIT();
    G_ISSUE(1); CP_COMMIT();
    G_ISSUE(2); CP_COMMIT();
    G_ISSUE(3); CP_COMMIT();

    for (int c = 0; c < NC; c++) {
        int st = c % NSTG;
        CP_WAIT3();                   // group c complete (<=3 pending)
        __syncthreads();              // stage c visible to all; stage c+4 free
        if (c + 4 < NC) G_ISSUE(c + 4);
        CP_COMMIT();
        uint32_t sa_st = sbase + st * STG_B;
        uint32_t sb_st = sbB   + st * STG_B;
#pragma unroll
        for (int ks = 0; ks < 2; ks++) {
            uint32_t kof = ks * 32;
            uint32_t b01[4], b23[4];
            ldmx4(b01, sb_st + boff + kof);
            ldmx4(b23, sb_st + boff + 16 * 80 + kof);
#pragma unroll
            for (int mt = 0; mt < 4; mt++) {
                uint32_t af[4];
                ldmx4(af, sa_st + aoff + mt * 16 * 80 + kof);
                mma16816(acc[mt][0], af, b01[0], b01[1]);
                mma16816(acc[mt][1], af, b01[2], b01[3]);
                mma16816(acc[mt][2], af, b23[0], b23[1]);
                mma16816(acc[mt][3], af, b23[2], b23[3]);
            }
        }
    }
#undef G_ISSUE

#pragma unroll
    for (int mt = 0; mt < 4; mt++) {
#pragma unroll
        for (int nt = 0; nt < 4; nt++) {
            int gm = m0 + wm + mt * 16 + qr;
            int gn = n0 + wn + nt * 8 + qc;
            float* d = acc[mt][nt];
            if (GEMM == 0) {
                float2 o0 = make_float2(silu_f(d[0]), silu_f(d[1]));
                float2 o1 = make_float2(silu_f(d[2]), silu_f(d[3]));
                *(float2*)(outp + (size_t)gm * LDC + gn) = o0;
                *(float2*)(outp + (size_t)(gm + 8) * LDC + gn) = o1;
            } else {
                float2 xa0 = *(const float2*)(x + (size_t)gm * DD + gn);
                float2 xa1 = *(const float2*)(x + (size_t)(gm + 8) * DD + gn);
                float2 rr  = *(const float2*)(res + gn);
                float2 o0 = make_float2(d[0] + xa0.x * rr.x, d[1] + xa0.y * rr.y);
                float2 o1 = make_float2(d[2] + xa1.x * rr.x, d[3] + xa1.y * rr.y);
                *(float2*)(outp + (size_t)gm * LDC + gn) = o0;
                *(float2*)(outp + (size_t)(gm + 8) * LDC + gn) = o1;
            }
        }
    }
}

// ---------------- attention v4 (unchanged from round 10 — validated) ---------
#define O_QH   0
#define O_QL   19584
#define O_KH   39168
#define O_KL   58752
#define O_KERH 0
#define O_KERL 21888
#define O_VTH  43776
#define O_VTL  63360
#define AT_SMEM_BYTES (82944 * 2)
#define SQK 136
#define SKR 152
#define SQKB 272
#define SKRB 304
#define SV   136
#define SVB  272

__global__ __launch_bounds__(576, 1)
void k_attn4(const float* __restrict__ gamma, const float* __restrict__ beta) {
    extern __shared__ __align__(16) __nv_bfloat16 sb[];
    uint32_t sbu = smem_u32(sb);
    int b = blockIdx.x, tid = threadIdx.x;
    int w = tid >> 5, lane = tid & 31;
    int w2 = w >> 1, half = w & 1;
    int qr = lane >> 2, qc = (lane & 3) * 2;
    int m = w2 * 16 + qr;
    const float* uvb = g_uv + (size_t)b * TT * NUV;

    uint32_t aoffQ = (uint32_t)((w2 * 16 + (lane & 7) + ((lane >> 3) & 1) * 8) * SQKB
                                + ((lane >> 4) & 1) * 16);
    uint32_t boffQ = (uint32_t)((((lane >> 4) & 1) * 8 + (lane & 7)) * SQKB
                                + ((lane >> 3) & 1) * 16);
    uint32_t aoffR = (uint32_t)((w2 * 16 + (lane & 7) + ((lane >> 3) & 1) * 8) * SKRB
                                + ((lane >> 4) & 1) * 16);
    uint32_t boffV = (uint32_t)(((lane & 7) + ((lane >> 3) & 1) * 8) * SVB
                                + ((lane >> 4) & 1) * 16);

    // ---- phase A ----
    for (int idx = tid; idx < 144 * 32; idx += 576) {
        int i = idx >> 5, s4 = (idx & 31) * 4;
        bool valid = (i < TT);
        float4 base = valid ? *(const float4*)(uvb + (size_t)i * NUV + 2*EE + s4)
                            : make_float4(0.f, 0.f, 0.f, 0.f);
        float4 ga = *(const float4*)(gamma + s4);
        float4 gk = *(const float4*)(gamma + SS + s4);
        float4 ba = *(const float4*)(beta + s4);
        float4 bk = *(const float4*)(beta + SS + s4);
        float q[4], k[4];
        q[0] = valid ? fmaf(base.x, ga.x, ba.x) : 0.f;
        q[1] = valid ? fmaf(base.y, ga.y, ba.y) : 0.f;
        q[2] = valid ? fmaf(base.z, ga.z, ba.z) : 0.f;
        q[3] = valid ? fmaf(base.w, ga.w, ba.w) : 0.f;
        k[0] = valid ? fmaf(base.x, gk.x, bk.x) : 0.f;
        k[1] = valid ? fmaf(base.y, gk.y, bk.y) : 0.f;
        k[2] = valid ? fmaf(base.z, gk.z, bk.z) : 0.f;
        k[3] = valid ? fmaf(base.w, gk.w, bk.w) : 0.f;
        __nv_bfloat16 qh[4], ql[4], kh[4], kl[4];
#pragma unroll
        for (int t = 0; t < 4; t++) { split1(q[t], qh[t], ql[t]); split1(k[t], kh[t], kl[t]); }
        int off = i * SQK + s4;
        *(__nv_bfloat162*)(sb + O_QH + off)     = __nv_bfloat162(qh[0], qh[1]);
        *(__nv_bfloat162*)(sb + O_QH + off + 2) = __nv_bfloat162(qh[2], qh[3]);
        *(__nv_bfloat162*)(sb + O_QL + off)     = __nv_bfloat162(ql[0], ql[1]);
        *(__nv_bfloat162*)(sb + O_QL + off + 2) = __nv_bfloat162(ql[2], ql[3]);
        *(__nv_bfloat162*)(sb + O_KH + off)     = __nv_bfloat162(kh[0], kh[1]);
        *(__nv_bfloat162*)(sb + O_KH + off + 2) = __nv_bfloat162(kh[2], kh[3]);
        *(__nv_bfloat162*)(sb + O_KL + off)     = __nv_bfloat162(kl[0], kl[1]);
        *(__nv_bfloat162*)(sb + O_KL + off + 2) = __nv_bfloat162(kl[2], kl[3]);
    }
    __syncthreads();

    // ---- scores ----
    const int np    = half ? 5 : 4;
    const int pbase = half ? 4 : 0;
    float acc[10][4];
#pragma unroll
    for (int i = 0; i < 10; i++)
#pragma unroll
        for (int t = 0; t < 4; t++) acc[i][t] = 0.f;

#pragma unroll
    for (int t = 0; t < 3; t++) {
        uint32_t Abase = sbu + ((t == 1) ? O_QL : O_QH) * 2;
        uint32_t Bbase = sbu + ((t == 2) ? O_KL : O_KH) * 2;
#pragma unroll
        for (int ks = 0; ks < 8; ks++) {
            uint32_t kof = ks * 32;
            uint32_t af[4];
            ldmx4(af, Abase + aoffQ + kof);
#pragma unroll
            for (int j = 0; j < 5; j++) {
                if (j < np) {
                    uint32_t bb[4];
                    ldmx4(bb, Bbase + boffQ + (uint32_t)(pbase + j) * 16 * SQKB + kof);
                    mma16816(acc[2*j],     af, bb[0], bb[1]);
                    mma16816(acc[2*j + 1], af, bb[2], bb[3]);
                }
            }
        }
    }
    __syncthreads();

    // ---- kern = relu(scores/sqrt(S))^2, split-store ----
#pragma unroll
    for (int j = 0; j < 5; j++) {
        if (j < np) {
#pragma unroll
            for (int s = 0; s < 2; s++) {
                int col = ((pbase + j) * 2 + s) * 8 + qc;
#pragma unroll
                for (int p = 0; p < 2; p++) {
                    int row = m + p * 8;
                    float v0 = fmaxf(acc[2*j + s][2*p]     * INV_SQRT_S, 0.f);
                    float v1 = fmaxf(acc[2*j + s][2*p + 1] * INV_SQRT_S, 0.f);
                    v0 *= v0; v1 *= v1;
                    __nv_bfloat16 h0, l0, h1, l1;
                    split1(v0, h0, l0); split1(v1, h1, l1);
                    *(__nv_bfloat162*)(sb + O_KERH + row * SKR + col) = __nv_bfloat162(h0, h1);
                    *(__nv_bfloat162*)(sb + O_KERL + row * SKR + col) = __nv_bfloat162(l0, l1);
                }
            }
        }
    }
    __syncthreads();

    // ---- attn chunks ----
    float* bounce = (float*)(sb + O_VTH);
    for (int ch = 0; ch < 4; ch++) {
        int e0 = ch * 128;
        for (int idx = tid; idx < 144 * 32; idx += 576) {
            int j = idx >> 5, e4 = (idx & 31) * 4;
            float4 v = (j < TT) ? *(const float4*)(uvb + (size_t)j * NUV + EE + e0 + e4)
                                : make_float4(0.f, 0.f, 0.f, 0.f);
            __nv_bfloat16 h0,h1,h2,h3,l0,l1,l2,l3;
            split1(v.x,h0,l0); split1(v.y,h1,l1); split1(v.z,h2,l2); split1(v.w,h3,l3);
            int off = j * SV + e4;
            *(__nv_bfloat162*)(sb + O_VTH + off)     = __nv_bfloat162(h0, h1);
            *(__nv_bfloat162*)(sb + O_VTH + off + 2) = __nv_bfloat162(h2, h3);
            *(__nv_bfloat162*)(sb + O_VTL + off)     = __nv_bfloat162(l0, l1);
            *(__nv_bfloat162*)(sb + O_VTL + off + 2) = __nv_bfloat162(l2, l3);
        }
        __syncthreads();

        float acc2[8][4];
#pragma unroll
        for (int i = 0; i < 8; i++)
#pragma unroll
            for (int t = 0; t < 4; t++) acc2[i][t] = 0.f;

#pragma unroll
        for (int t = 0; t < 3; t++) {
            uint32_t Abase = sbu + ((t == 1) ? O_KERL : O_KERH) * 2;
            uint32_t Bbase = sbu + ((t == 2) ? O_VTL : O_VTH) * 2;
#pragma unroll
            for (int kt = 0; kt < 9; kt++) {
                uint32_t kof = (uint32_t)kt * 16 * SVB;
                uint32_t af[4];
                ldmx4(af, Abase + aoffR + (uint32_t)kt * 32);
#pragma unroll
                for (int j = 0; j < 4; j++) {
                    uint32_t bb[4];
                    ldmx4t(bb, Bbase + boffV + kof + (uint32_t)(4 * half + j) * 32);
                    mma16816(acc2[2*j],     af, bb[0], bb[1]);
                    mma16816(acc2[2*j + 1], af, bb[2], bb[3]);
                }
            }
        }
        __syncthreads();

#pragma unroll
        for (int j = 0; j < 4; j++) {
#pragma unroll
            for (int s = 0; s < 2; s++) {
                int colb = ((4 * half + j) * 2 + s) * 8 + qc;
#pragma unroll
                for (int p = 0; p < 2; p++) {
                    int row = m + p * 8;
                    *(float2*)(bounce + row * 132 + colb) =
                        make_float2(acc2[2*j + s][2*p], acc2[2*j + s][2*p + 1]);
                }
            }
        }
        __syncthreads();

        for (int idx = tid; idx < TT * 32; idx += 576) {
            int row = idx >> 5, c4 = (idx & 31) * 4;
            float4 a = *(const float4*)(bounce + row * 132 + c4);
            float4 u = *(const float4*)(uvb + (size_t)row * NUV + e0 + c4);
            float h0 = a.x * u.x, h1 = a.y * u.y, h2 = a.z * u.z, h3 = a.w * u.w;
            __nv_bfloat16 hh0,hl0,hh1,hl1,hh2,hl2,hh3,hl3;
            split1(h0,hh0,hl0); split1(h1,hh1,hl1);
            split1(h2,hh2,hl2); split1(h3,hh3,hl3);
            size_t ro = (size_t)(b * TT + row) * EE + e0 + c4;
            __nv_bfloat162* dh = (__nv_bfloat162*)(g_hh + ro);
            __nv_bfloat162* dl = (__nv_bfloat162*)(g_hl + ro);
            dh[0] = __nv_bfloat162(hh0, hh1); dh[1] = __nv_bfloat162(hh2, hh3);
            dl[0] = __nv_bfloat162(hl0, hl1); dl[1] = __nv_bfloat162(hl2, hl3);
        }
        __syncthreads();
    }
}

// ---------------- launch ----------------------------------------------------
extern "C" void kernel_launch(void* const* d_in, const int* in_sizes, int n_in,
                              void* d_out, int out_size) {
    (void)in_sizes; (void)n_in; (void)out_size;
    const float* x     = (const float*)d_in[0];
    const float* W_uv  = (const float*)d_in[1];
    const float* W_o   = (const float*)d_in[2];
    const float* gamma = (const float*)d_in[3];
    const float* beta  = (const float*)d_in[4];
    const float* g     = (const float*)d_in[5];
    const float* res   = (const float*)d_in[6];
    float* out = (float*)d_out;

    cudaFuncSetAttribute(k_attn4, cudaFuncAttributeMaxDynamicSharedMemorySize,
                         AT_SMEM_BYTES);
    cudaFuncSetAttribute(k_gemm_mma<0>, cudaFuncAttributeMaxDynamicSharedMemorySize,
                         GM_SMEM);
    cudaFuncSetAttribute(k_gemm_mma<1>, cudaFuncAttributeMaxDynamicSharedMemorySize,
                         GM_SMEM);

    k_rnorm_split<<<MTOT / 8, dim3(32, 8)>>>(x, g);
    k_split_w<<<(NUV * 64 + DD * 128 + 255) / 256, 256>>>(W_uv, W_o);
    k_gemm_mma<0><<<dim3(NUV / 128, MTOT / 128), 256, GM_SMEM>>>(nullptr, nullptr, nullptr);
    k_attn4<<<BATCH, 576, AT_SMEM_BYTES>>>(gamma, beta);
    k_gemm_mma<1><<<dim3(DD / 128, MTOT / 128), 256, GM_SMEM>>>(x, res, out);
}

// round 12
// speedup vs baseline: 1.4619x; 1.4619x over previous
#include <cuda_runtime.h>
#include <cuda_fp16.h>
#include <cstdint>

#define BATCH 1024
#define TT    133
#define DD    256
#define EE    512
#define SS    128
#define NUV   1152
#define MTOT  (BATCH*TT)     // 136192
#define INV_SQRT_S 0.08838834764831845f
#define EPSV  1e-5f

// ---------------- scratch ----------------------------------------------------
__device__ float g_uv[(size_t)MTOT * NUV];
__device__ __align__(16) __half g_xh[(size_t)MTOT * DD];
__device__ __align__(16) __half g_xl[(size_t)MTOT * DD];
__device__ __align__(16) __half g_wh[(size_t)NUV * DD];      // W_uv fp16 (single)
__device__ __align__(16) __half g_woh[(size_t)DD * EE];      // W_o fp16 (single)
__device__ __align__(16) __half g_hh[(size_t)MTOT * EE];
__device__ __align__(16) __half g_hl[(size_t)MTOT * EE];

// ---------------- helpers ----------------------------------------------------
__device__ __forceinline__ uint32_t smem_u32(const void* p) {
    uint32_t a;
    asm("{ .reg .u64 t; cvta.to.shared.u64 t, %1; cvt.u32.u64 %0, t; }"
        : "=r"(a) : "l"(p));
    return a;
}
__device__ __forceinline__ float silu_f(float v) { return v / (1.0f + __expf(-v)); }
__device__ __forceinline__ void split1h(float v, __half &h, __half &l) {
    h = __float2half_rn(v);
    l = __float2half_rn(v - __half2float(h));
}
__device__ __forceinline__ void mma16816(float (&d)[4], const uint32_t (&a)[4],
                                         uint32_t b0, uint32_t b1) {
    asm volatile("mma.sync.aligned.m16n8k16.row.col.f32.f16.f16.f32 "
                 "{%0,%1,%2,%3}, {%4,%5,%6,%7}, {%8,%9}, {%0,%1,%2,%3};"
                 : "+f"(d[0]), "+f"(d[1]), "+f"(d[2]), "+f"(d[3])
                 : "r"(a[0]), "r"(a[1]), "r"(a[2]), "r"(a[3]), "r"(b0), "r"(b1));
}
__device__ __forceinline__ void ldmx4(uint32_t (&r)[4], uint32_t addr) {
    asm volatile("ldmatrix.sync.aligned.m8n8.x4.shared.b16 {%0,%1,%2,%3}, [%4];"
                 : "=r"(r[0]), "=r"(r[1]), "=r"(r[2]), "=r"(r[3]) : "r"(addr));
}
__device__ __forceinline__ void ldmx4t(uint32_t (&r)[4], uint32_t addr) {
    asm volatile("ldmatrix.sync.aligned.m8n8.x4.trans.shared.b16 {%0,%1,%2,%3}, [%4];"
                 : "=r"(r[0]), "=r"(r[1]), "=r"(r[2]), "=r"(r[3]) : "r"(addr));
}
#define CP_ASYNC16(s, g) \
    asm volatile("cp.async.cg.shared.global [%0], [%1], 16;" :: "r"(s), "l"(g))
#define CP_COMMIT() asm volatile("cp.async.commit_group;")
#define CP_WAIT1()  asm volatile("cp.async.wait_group 1;")

// ---------------- fused rnorm + x split (fp16 2-term) -------------------------
__global__ void k_rnorm_split(const float* __restrict__ x, const float* __restrict__ g) {
    int row = blockIdx.x * 8 + threadIdx.y;
    int lane = threadIdx.x;
    const float4* xr = (const float4*)(x + (size_t)row * DD);
    float4 v0 = xr[lane], v1 = xr[lane + 32];
    float s = v0.x*v0.x + v0.y*v0.y + v0.z*v0.z + v0.w*v0.w
            + v1.x*v1.x + v1.y*v1.y + v1.z*v1.z + v1.w*v1.w;
#pragma unroll
    for (int o = 16; o; o >>= 1) s += __shfl_xor_sync(0xffffffffu, s, o);
    float sc = g[0] / fmaxf(sqrtf(s) * 0.0625f, EPSV);
    size_t base = (size_t)row * 64;
#pragma unroll
    for (int half_ = 0; half_ < 2; half_++) {
        float4 v = half_ ? v1 : v0;
        size_t idx = base + lane + half_ * 32;
        __half h0,h1,h2,h3,l0,l1,l2,l3;
        split1h(v.x*sc,h0,l0); split1h(v.y*sc,h1,l1);
        split1h(v.z*sc,h2,l2); split1h(v.w*sc,h3,l3);
        __half2* dh = (__half2*)(g_xh + idx*4);
        __half2* dl = (__half2*)(g_xl + idx*4);
        dh[0] = __halves2half2(h0,h1); dh[1] = __halves2half2(h2,h3);
        dl[0] = __halves2half2(l0,l1); dl[1] = __halves2half2(l2,l3);
    }
}

// ---------------- weight cast to fp16 (single) --------------------------------
__global__ void k_split_w(const float* __restrict__ Wuv, const float* __restrict__ Wo) {
    int idx = blockIdx.x * 256 + threadIdx.x;
    const int N1 = NUV * DD / 4;
    const int N2 = DD * EE / 4;
    if (idx < N1) {
        float4 v = ((const float4*)Wuv)[idx];
        __half2* ph = (__half2*)(g_wh + (size_t)idx*4);
        ph[0] = __halves2half2(__float2half_rn(v.x), __float2half_rn(v.y));
        ph[1] = __halves2half2(__float2half_rn(v.z), __float2half_rn(v.w));
    } else if (idx < N1 + N2) {
        int j = idx - N1;
        float4 v = ((const float4*)Wo)[j];
        __half2* ph = (__half2*)(g_woh + (size_t)j*4);
        ph[0] = __halves2half2(__float2half_rn(v.x), __float2half_rn(v.y));
        ph[1] = __halves2half2(__float2half_rn(v.z), __float2half_rn(v.w));
    }
}

// ---------------- GEMMs: fp16 2-term, 3-stage cp.async ------------------------
// GEMM==0: g_uv = silu([xh|xl] @ wh^T), K=256, N=1152
// GEMM==1: out  = [hh|hl] @ woh^T + x*res, K=512, N=256
#define STG_B    10240                 // one 128x32 tile (128*40*2 bytes)
#define GM_SMEM  (6 * STG_B)           // 61440 bytes

template<int GEMM>
__global__ __launch_bounds__(256, 2)
void k_gemm_mma(const float* __restrict__ x, const float* __restrict__ res,
                float* __restrict__ outp_param) {
    constexpr int KREAL = (GEMM == 0) ? 256 : 512;
    constexpr int LDC   = (GEMM == 0) ? NUV : DD;
    constexpr int KC    = KREAL / 32;
    constexpr int NC    = 2 * KC;           // 2 split terms
    const __half* Ah = (GEMM == 0) ? g_xh : g_hh;
    const __half* Al = (GEMM == 0) ? g_xl : g_hl;
    const __half* Bh = (GEMM == 0) ? g_wh : g_woh;
    float* outp = (GEMM == 0) ? g_uv : outp_param;   // device-side symbol ref!

    extern __shared__ __align__(16) char smc[];
    uint32_t sbase = smem_u32(smc);
    uint32_t sbB   = sbase + 3 * STG_B;

    int tid = threadIdx.x, lane = tid & 31, wid = tid >> 5;
    int m0 = blockIdx.y * 128, n0 = blockIdx.x * 128;
    int wm = (wid & 1) * 64, wn = (wid >> 1) * 32;
    int qr = lane >> 2, qc = (lane & 3) * 2;

    int lrow = (tid * 2) >> 2;
    int lu   = (tid * 2) & 3;
    uint32_t soff0 = lrow * 80 + lu * 16;
    uint32_t soff1 = lrow * 80 + (lu + 1) * 16;

    uint32_t aoff = (uint32_t)((wm + (lane & 7) + ((lane >> 3) & 1) * 8) * 80
                               + ((lane >> 4) & 1) * 16);
    uint32_t boff = (uint32_t)((wn + ((lane >> 4) & 1) * 8 + (lane & 7)) * 80
                               + ((lane >> 3) & 1) * 16);

    float acc[4][4][4];
#pragma unroll
    for (int i = 0; i < 4; i++)
#pragma unroll
        for (int j = 0; j < 4; j++)
#pragma unroll
            for (int k = 0; k < 4; k++) acc[i][j][k] = 0.f;

#define G_ISSUE(c) do { \
    int st_ = (c) % 3; \
    int term = (c) / KC; \
    int kk = ((c) % KC) * 32; \
    const __half* a_ = term ? Al : Ah; \
    uint32_t sa_ = sbase + st_ * STG_B; \
    uint32_t sb_ = sbB   + st_ * STG_B; \
    CP_ASYNC16(sa_ + soff0, a_ + (size_t)(m0 + lrow) * KREAL + kk + lu * 8); \
    CP_ASYNC16(sa_ + soff1, a_ + (size_t)(m0 + lrow) * KREAL + kk + (lu + 1) * 8); \
    CP_ASYNC16(sb_ + soff0, Bh + (size_t)(n0 + lrow) * KREAL + kk + lu * 8); \
    CP_ASYNC16(sb_ + soff1, Bh + (size_t)(n0 + lrow) * KREAL + kk + (lu + 1) * 8); \
} while (0)

    G_ISSUE(0); CP_COMMIT();
    G_ISSUE(1); CP_COMMIT();

    for (int c = 0; c < NC; c++) {
        int st = c % 3;
        CP_WAIT1();
        __syncthreads();
        uint32_t sa_st = sbase + st * STG_B;
        uint32_t sb_st = sbB   + st * STG_B;
#pragma unroll
        for (int ks = 0; ks < 2; ks++) {
            uint32_t kof = ks * 32;
            uint32_t b01[4], b23[4];
            ldmx4(b01, sb_st + boff + kof);
            ldmx4(b23, sb_st + boff + 16 * 80 + kof);
#pragma unroll
            for (int mt = 0; mt < 4; mt++) {
                uint32_t af[4];
                ldmx4(af, sa_st + aoff + mt * 16 * 80 + kof);
                mma16816(acc[mt][0], af, b01[0], b01[1]);
                mma16816(acc[mt][1], af, b01[2], b01[3]);
                mma16816(acc[mt][2], af, b23[0], b23[1]);
                mma16816(acc[mt][3], af, b23[2], b23[3]);
            }
        }
        if (c + 2 < NC) G_ISSUE(c + 2);
        CP_COMMIT();
    }
#undef G_ISSUE

#pragma unroll
    for (int mt = 0; mt < 4; mt++) {
#pragma unroll
        for (int nt = 0; nt < 4; nt++) {
            int gm = m0 + wm + mt * 16 + qr;
            int gn = n0 + wn + nt * 8 + qc;
            float* d = acc[mt][nt];
            if (GEMM == 0) {
                float2 o0 = make_float2(silu_f(d[0]), silu_f(d[1]));
                float2 o1 = make_float2(silu_f(d[2]), silu_f(d[3]));
                *(float2*)(outp + (size_t)gm * LDC + gn) = o0;
                *(float2*)(outp + (size_t)(gm + 8) * LDC + gn) = o1;
            } else {
                float2 xa0 = *(const float2*)(x + (size_t)gm * DD + gn);
                float2 xa1 = *(const float2*)(x + (size_t)(gm + 8) * DD + gn);
                float2 rr  = *(const float2*)(res + gn);
                float2 o0 = make_float2(d[0] + xa0.x * rr.x, d[1] + xa0.y * rr.y);
                float2 o1 = make_float2(d[2] + xa1.x * rr.x, d[3] + xa1.y * rr.y);
                *(float2*)(outp + (size_t)gm * LDC + gn) = o0;
                *(float2*)(outp + (size_t)(gm + 8) * LDC + gn) = o1;
            }
        }
    }
}

// ---------------- attention v5: fp16 2-term ----------------------------------
// smem (fp16 elem offsets):
//   phase A: qh[144][136]@0, ql@19584, k[144][136]@39168  (end 58752)
//   phase B: kernh[144][152]@0, kernl@21888 (end 43776)
//            v[144][136]@43776 (end 63360)
//   bounce fp32 [144][132] overlays @43776 (38016 elem -> end 81792)
#define O_QH   0
#define O_QL   19584
#define O_K    39168
#define O_KERH 0
#define O_KERL 21888
#define O_V    43776
#define AT_SMEM_BYTES (81792 * 2)
#define SQK 136
#define SKR 152
#define SQKB 272
#define SKRB 304
#define SV   136
#define SVB  272

__global__ __launch_bounds__(576, 1)
void k_attn5(const float* __restrict__ gamma, const float* __restrict__ beta) {
    extern __shared__ __align__(16) __half sb[];
    uint32_t sbu = smem_u32(sb);
    int b = blockIdx.x, tid = threadIdx.x;
    int w = tid >> 5, lane = tid & 31;
    int w2 = w >> 1, half_ = w & 1;
    int qr = lane >> 2, qc = (lane & 3) * 2;
    int m = w2 * 16 + qr;
    const float* uvb = g_uv + (size_t)b * TT * NUV;

    uint32_t aoffQ = (uint32_t)((w2 * 16 + (lane & 7) + ((lane >> 3) & 1) * 8) * SQKB
                                + ((lane >> 4) & 1) * 16);
    uint32_t boffQ = (uint32_t)((((lane >> 4) & 1) * 8 + (lane & 7)) * SQKB
                                + ((lane >> 3) & 1) * 16);
    uint32_t aoffR = (uint32_t)((w2 * 16 + (lane & 7) + ((lane >> 3) & 1) * 8) * SKRB
                                + ((lane >> 4) & 1) * 16);
    uint32_t boffV = (uint32_t)(((lane & 7) + ((lane >> 3) & 1) * 8) * SVB
                                + ((lane >> 4) & 1) * 16);

    // ---- phase A: q hi/lo + k single, rows >= TT zeroed ----
    for (int idx = tid; idx < 144 * 32; idx += 576) {
        int i = idx >> 5, s4 = (idx & 31) * 4;
        bool valid = (i < TT);
        float4 base = valid ? *(const float4*)(uvb + (size_t)i * NUV + 2*EE + s4)
                            : make_float4(0.f, 0.f, 0.f, 0.f);
        float4 ga = *(const float4*)(gamma + s4);
        float4 gk = *(const float4*)(gamma + SS + s4);
        float4 ba = *(const float4*)(beta + s4);
        float4 bk = *(const float4*)(beta + SS + s4);
        float q[4], k[4];
        q[0] = valid ? fmaf(base.x, ga.x, ba.x) : 0.f;
        q[1] = valid ? fmaf(base.y, ga.y, ba.y) : 0.f;
        q[2] = valid ? fmaf(base.z, ga.z, ba.z) : 0.f;
        q[3] = valid ? fmaf(base.w, ga.w, ba.w) : 0.f;
        k[0] = valid ? fmaf(base.x, gk.x, bk.x) : 0.f;
        k[1] = valid ? fmaf(base.y, gk.y, bk.y) : 0.f;
        k[2] = valid ? fmaf(base.z, gk.z, bk.z) : 0.f;
        k[3] = valid ? fmaf(base.w, gk.w, bk.w) : 0.f;
        __half qh[4], ql[4];
#pragma unroll
        for (int t = 0; t < 4; t++) split1h(q[t], qh[t], ql[t]);
        int off = i * SQK + s4;
        *(__half2*)(sb + O_QH + off)     = __halves2half2(qh[0], qh[1]);
        *(__half2*)(sb + O_QH + off + 2) = __halves2half2(qh[2], qh[3]);
        *(__half2*)(sb + O_QL + off)     = __halves2half2(ql[0], ql[1]);
        *(__half2*)(sb + O_QL + off + 2) = __halves2half2(ql[2], ql[3]);
        *(__half2*)(sb + O_K + off)      = __halves2half2(__float2half_rn(k[0]), __float2half_rn(k[1]));
        *(__half2*)(sb + O_K + off + 2)  = __halves2half2(__float2half_rn(k[2]), __float2half_rn(k[3]));
    }
    __syncthreads();

    // ---- scores: 2 terms (qh·k, ql·k) ----
    const int np    = half_ ? 5 : 4;
    const int pbase = half_ ? 4 : 0;
    float acc[10][4];
#pragma unroll
    for (int i = 0; i < 10; i++)
#pragma unroll
        for (int t = 0; t < 4; t++) acc[i][t] = 0.f;

#pragma unroll
    for (int t = 0; t < 2; t++) {
        uint32_t Abase = sbu + (t ? O_QL : O_QH) * 2;
        uint32_t Bbase = sbu + O_K * 2;
#pragma unroll
        for (int ks = 0; ks < 8; ks++) {
            uint32_t kof = ks * 32;
            uint32_t af[4];
            ldmx4(af, Abase + aoffQ + kof);
#pragma unroll
            for (int j = 0; j < 5; j++) {
                if (j < np) {
                    uint32_t bb[4];
                    ldmx4(bb, Bbase + boffQ + (uint32_t)(pbase + j) * 16 * SQKB + kof);
                    mma16816(acc[2*j],     af, bb[0], bb[1]);
                    mma16816(acc[2*j + 1], af, bb[2], bb[3]);
                }
            }
        }
    }
    __syncthreads();

    // ---- kern = relu(scores/sqrt(S))^2, fp16 hi/lo split-store ----
#pragma unroll
    for (int j = 0; j < 5; j++) {
        if (j < np) {
#pragma unroll
            for (int s = 0; s < 2; s++) {
                int col = ((pbase + j) * 2 + s) * 8 + qc;
#pragma unroll
                for (int p = 0; p < 2; p++) {
                    int row = m + p * 8;
                    float v0 = fmaxf(acc[2*j + s][2*p]     * INV_SQRT_S, 0.f);
                    float v1 = fmaxf(acc[2*j + s][2*p + 1] * INV_SQRT_S, 0.f);
                    v0 *= v0; v1 *= v1;
                    __half h0, l0, h1, l1;
                    split1h(v0, h0, l0); split1h(v1, h1, l1);
                    *(__half2*)(sb + O_KERH + row * SKR + col) = __halves2half2(h0, h1);
                    *(__half2*)(sb + O_KERL + row * SKR + col) = __halves2half2(l0, l1);
                }
            }
        }
    }
    __syncthreads();

    // ---- attn chunks: kern(hi/lo) @ v(single) ----
    float* bounce = (float*)(sb + O_V);
    for (int ch = 0; ch < 4; ch++) {
        int e0 = ch * 128;
        for (int idx = tid; idx < 144 * 32; idx += 576) {
            int j = idx >> 5, e4 = (idx & 31) * 4;
            float4 v = (j < TT) ? *(const float4*)(uvb + (size_t)j * NUV + EE + e0 + e4)
                                : make_float4(0.f, 0.f, 0.f, 0.f);
            int off = j * SV + e4;
            *(__half2*)(sb + O_V + off)     = __halves2half2(__float2half_rn(v.x), __float2half_rn(v.y));
            *(__half2*)(sb + O_V + off + 2) = __halves2half2(__float2half_rn(v.z), __float2half_rn(v.w));
        }
        __syncthreads();

        float acc2[8][4];
#pragma unroll
        for (int i = 0; i < 8; i++)
#pragma unroll
            for (int t = 0; t < 4; t++) acc2[i][t] = 0.f;

#pragma unroll
        for (int t = 0; t < 2; t++) {
            uint32_t Abase = sbu + (t ? O_KERL : O_KERH) * 2;
            uint32_t Bbase = sbu + O_V * 2;
#pragma unroll
            for (int kt = 0; kt < 9; kt++) {
                uint32_t kof = (uint32_t)kt * 16 * SVB;
                uint32_t af[4];
                ldmx4(af, Abase + aoffR + (uint32_t)kt * 32);
#pragma unroll
                for (int j = 0; j < 4; j++) {
                    uint32_t bb[4];
                    ldmx4t(bb, Bbase + boffV + kof + (uint32_t)(4 * half_ + j) * 32);
                    mma16816(acc2[2*j],     af, bb[0], bb[1]);
                    mma16816(acc2[2*j + 1], af, bb[2], bb[3]);
                }
            }
        }
        __syncthreads();   // all mma reads of v done before bounce overwrite

#pragma unroll
        for (int j = 0; j < 4; j++) {
#pragma unroll
            for (int s = 0; s < 2; s++) {
                int colb = ((4 * half_ + j) * 2 + s) * 8 + qc;
#pragma unroll
                for (int p = 0; p < 2; p++) {
                    int row = m + p * 8;
                    *(float2*)(bounce + row * 132 + colb) =
                        make_float2(acc2[2*j + s][2*p], acc2[2*j + s][2*p + 1]);
                }
            }
        }
        __syncthreads();

        // coalesced epilogue: h = u * attn, fp16 split, 4B stores
        for (int idx = tid; idx < TT * 32; idx += 576) {
            int row = idx >> 5, c4 = (idx & 31) * 4;
            float4 a = *(const float4*)(bounce + row * 132 + c4);
            float4 u = *(const float4*)(uvb + (size_t)row * NUV + e0 + c4);
            float h0 = a.x * u.x, h1 = a.y * u.y, h2 = a.z * u.z, h3 = a.w * u.w;
            __half hh0,hl0,hh1,hl1,hh2,hl2,hh3,hl3;
            split1h(h0,hh0,hl0); split1h(h1,hh1,hl1);
            split1h(h2,hh2,hl2); split1h(h3,hh3,hl3);
            size_t ro = (size_t)(b * TT + row) * EE + e0 + c4;
            __half2* dh = (__half2*)(g_hh + ro);
            __half2* dl = (__half2*)(g_hl + ro);
            dh[0] = __halves2half2(hh0, hh1); dh[1] = __halves2half2(hh2, hh3);
            dl[0] = __halves2half2(hl0, hl1); dl[1] = __halves2half2(hl2, hl3);
        }
        __syncthreads();   // bounce/v reads done before next chunk fill
    }
}

// ---------------- launch ----------------------------------------------------
extern "C" void kernel_launch(void* const* d_in, const int* in_sizes, int n_in,
                              void* d_out, int out_size) {
    (void)in_sizes; (void)n_in; (void)out_size;
    const float* x     = (const float*)d_in[0];
    const float* W_uv  = (const float*)d_in[1];
    const float* W_o   = (const float*)d_in[2];
    const float* gamma = (const float*)d_in[3];
    const float* beta  = (const float*)d_in[4];
    const float* g     = (const float*)d_in[5];
    const float* res   = (const float*)d_in[6];
    float* out = (float*)d_out;

    cudaFuncSetAttribute(k_attn5, cudaFuncAttributeMaxDynamicSharedMemorySize,
                         AT_SMEM_BYTES);
    cudaFuncSetAttribute(k_gemm_mma<0>, cudaFuncAttributeMaxDynamicSharedMemorySize,
                         GM_SMEM);
    cudaFuncSetAttribute(k_gemm_mma<1>, cudaFuncAttributeMaxDynamicSharedMemorySize,
                         GM_SMEM);

    k_rnorm_split<<<MTOT / 8, dim3(32, 8)>>>(x, g);
    k_split_w<<<(NUV * 64 + DD * 128 + 255) / 256, 256>>>(W_uv, W_o);
    k_gemm_mma<0><<<dim3(NUV / 128, MTOT / 128), 256, GM_SMEM>>>(nullptr, nullptr, nullptr);
    k_attn5<<<BATCH, 576, AT_SMEM_BYTES>>>(gamma, beta);
    k_gemm_mma<1><<<dim3(DD / 128, MTOT / 128), 256, GM_SMEM>>>(x, res, out);
}